// round 12
// baseline (speedup 1.0000x reference)
#include <cuda_runtime.h>
#include <cuda_fp16.h>
#include <cstdint>

// Problem constants
#define SLEN 1024
#define BSZ  64
#define DMODEL 1024
#define NH   16
#define DKH  64
#define M_TOT (SLEN * BSZ)   // 65536

// Scratch
__device__ float g_q[67108864];
__device__ float g_k[67108864];
__device__ float g_v[67108864];
__device__ float g_c[67108864];
__device__ __half g_whi[4 * 1048576];   // 4 weights, hi
__device__ __half g_wlo[4 * 1048576];   // 4 weights, lo

// ---------------------------------------------------------------------------
// PTX helpers
// ---------------------------------------------------------------------------
__device__ __forceinline__ uint32_t smem_u32(const void* p) {
    uint32_t a;
    asm("{ .reg .u64 t; cvta.to.shared.u64 t, %1; cvt.u32.u64 %0, t; }"
        : "=r"(a) : "l"(p));
    return a;
}
__device__ __forceinline__ void cp16(uint32_t dst, const void* src) {
    asm volatile("cp.async.cg.shared.global [%0], [%1], 16;"
                 :: "r"(dst), "l"(src));
}
#define CP_COMMIT() asm volatile("cp.async.commit_group;" ::: "memory")
#define CP_WAIT1()  asm volatile("cp.async.wait_group 1;" ::: "memory")
#define CP_WAIT0()  asm volatile("cp.async.wait_group 0;" ::: "memory")

__device__ __forceinline__ void ldsm_x4(uint32_t& r0, uint32_t& r1,
                                        uint32_t& r2, uint32_t& r3, uint32_t a) {
    asm volatile("ldmatrix.sync.aligned.m8n8.x4.shared.b16 {%0,%1,%2,%3}, [%4];"
                 : "=r"(r0), "=r"(r1), "=r"(r2), "=r"(r3) : "r"(a));
}
__device__ __forceinline__ void mma16816(float* d, const uint32_t* a,
                                         const uint32_t* b) {
    asm volatile(
        "mma.sync.aligned.m16n8k16.row.col.f32.f16.f16.f32 "
        "{%0,%1,%2,%3}, {%4,%5,%6,%7}, {%8,%9}, {%0,%1,%2,%3};"
        : "+f"(d[0]), "+f"(d[1]), "+f"(d[2]), "+f"(d[3])
        : "r"(a[0]), "r"(a[1]), "r"(a[2]), "r"(a[3]), "r"(b[0]), "r"(b[1]));
}

// ---------------------------------------------------------------------------
// All-weights split fp32 -> (hi, lo) fp16, one launch. blockIdx.y = weight.
// ---------------------------------------------------------------------------
__global__ void __launch_bounds__(256) split_all(
    const float* __restrict__ w0, const float* __restrict__ w1,
    const float* __restrict__ w2, const float* __restrict__ w3,
    __half* __restrict__ hi, __half* __restrict__ lo)
{
    const int wsel = blockIdx.y;
    const float* in = (wsel == 0) ? w0 : (wsel == 1) ? w1 :
                      (wsel == 2) ? w2 : w3;
    const int i = blockIdx.x * blockDim.x + threadIdx.x;   // 0..262143
    const float4 v = ((const float4*)in)[i];
    __half h0 = __float2half_rn(v.x);
    __half h1 = __float2half_rn(v.y);
    __half h2 = __float2half_rn(v.z);
    __half h3 = __float2half_rn(v.w);
    __half l0 = __float2half_rn(v.x - __half2float(h0));
    __half l1 = __float2half_rn(v.y - __half2float(h1));
    __half l2 = __float2half_rn(v.z - __half2float(h2));
    __half l3 = __float2half_rn(v.w - __half2float(h3));
    const size_t o = (size_t)wsel * 1048576 + (size_t)i * 4;
    __half2* hp = (__half2*)(hi + o);
    __half2* lp = (__half2*)(lo + o);
    hp[0] = __halves2half2(h0, h1);
    hp[1] = __halves2half2(h2, h3);
    lp[0] = __halves2half2(l0, l1);
    lp[1] = __halves2half2(l2, l3);
}

// ---------------------------------------------------------------------------
// fp16-split GEMM v7 = v5 config, batched over blockIdx.z.
// CTA tile 128x256, 16 warps (2m x 8n), warp tile 64x32, KC=64 (16 chunks).
// 2 stages x 108KB = 216KB smem, 1 CTA/SM, regs 128 (no spills).
// acc += Ahi*Whi + Ahi*Wlo + Alo*Whi  (fp32 accumulate).
// ---------------------------------------------------------------------------
#define KC 64
#define LDH 72                            // halves per smem row (144B stride)
#define ROWB (LDH * 2)                    // 144
#define A_TILE_B (128 * ROWB)             // 18432
#define B_TILE_B (256 * ROWB)             // 36864
#define OFF_ALO  (A_TILE_B)
#define OFF_BHI  (2 * A_TILE_B)
#define OFF_BLO  (2 * A_TILE_B + B_TILE_B)
#define STG_B    (2 * A_TILE_B + 2 * B_TILE_B)   // 110592
#define GEMM_SMEM (2 * STG_B)                    // 221184
#define NCHUNK 16
#define GT_THR 512

struct GemmBatch {
    const float* A[3];
    const float* bias[3];
    float*       C[3];
    const __half* Whi;   // base; weight w at +widx[z]*1048576
    const __half* Wlo;
    int widx[3];
};

__device__ __forceinline__ void ldgA(const float* __restrict__ A,
                                     int bm, int k0, int tid, float4* pf)
{
    #pragma unroll
    for (int p = 0; p < 4; p++) {
        const int idx = p * GT_THR + tid;   // 0..2047
        const int row = idx >> 4;           // 0..127
        const int q   = idx & 15;           // 16 float4 per 64-f32 row
        pf[p] = *(const float4*)(A + (size_t)(bm + row) * DMODEL + k0 + q * 4);
    }
}

__device__ __forceinline__ void stsA(char* smem_base, int stg_off,
                                     int tid, const float4* pf)
{
    #pragma unroll
    for (int p = 0; p < 4; p++) {
        const int idx = p * GT_THR + tid;
        const int row = idx >> 4;
        const int q   = idx & 15;
        const float4 v = pf[p];
        __half2 h01 = __floats2half2_rn(v.x, v.y);
        __half2 h23 = __floats2half2_rn(v.z, v.w);
        __half2 l01 = __floats2half2_rn(v.x - __low2float(h01),
                                        v.y - __high2float(h01));
        __half2 l23 = __floats2half2_rn(v.z - __low2float(h23),
                                        v.w - __high2float(h23));
        char* d = smem_base + stg_off + row * ROWB + q * 8;
        *(__half2*)(d)               = h01;
        *(__half2*)(d + 4)           = h23;
        *(__half2*)(d + OFF_ALO)     = l01;
        *(__half2*)(d + OFF_ALO + 4) = l23;
    }
}

__device__ __forceinline__ void cpB(uint32_t stg, const __half* __restrict__ Whi,
                                    const __half* __restrict__ Wlo,
                                    int bn, int k0, int tid)
{
    #pragma unroll
    for (int p = 0; p < 4; p++) {
        const int idx = p * GT_THR + tid;   // 0..2047
        const int row = idx >> 3;           // 0..255
        const int qq  = idx & 7;            // 8 x 16B per 64-half row
        const uint32_t d = stg + OFF_BHI + row * ROWB + qq * 16;
        const size_t g = (size_t)(bn + row) * DMODEL + k0 + qq * 8;
        cp16(d, Whi + g);
        cp16(d + (OFF_BLO - OFF_BHI), Wlo + g);
    }
}

__global__ void __launch_bounds__(GT_THR, 1) gemm_v7(GemmBatch p)
{
    extern __shared__ char smem[];
    const uint32_t sb = smem_u32(smem);
    const int tid = threadIdx.x;
    const int lane = tid & 31;
    const int wid = tid >> 5;
    const int z = blockIdx.z;
    const int bm = blockIdx.y * 128;
    const int bn = blockIdx.x * 256;
    const int wm = (wid & 1) * 64;
    const int wn = (wid >> 1) * 32;

    const float* A = p.A[z];
    const float* bias = p.bias[z];
    float* C = p.C[z];
    const __half* Whi = p.Whi + (size_t)p.widx[z] * 1048576;
    const __half* Wlo = p.Wlo + (size_t)p.widx[z] * 1048576;

    float acc[4][4][4];
    #pragma unroll
    for (int i = 0; i < 4; i++)
        #pragma unroll
        for (int j = 0; j < 4; j++)
            #pragma unroll
            for (int x = 0; x < 4; x++) acc[i][j][x] = 0.0f;

    float4 pf[4];

    // prologue: A(0) -> stage0, B(0)/B(1) in flight, pf <- A(1)
    ldgA(A, bm, 0, tid, pf);
    stsA(smem, 0, tid, pf);
    cpB(sb, Whi, Wlo, bn, 0, tid);
    CP_COMMIT();
    ldgA(A, bm, KC, tid, pf);
    cpB(sb + STG_B, Whi, Wlo, bn, KC, tid);
    CP_COMMIT();
    CP_WAIT1();
    __syncthreads();

    // fragment address components
    const int at = lane >> 3, ar = lane & 7;
    const int a_row_off = ((at & 1) << 3) + ar;
    const int a_kcol8   = ((at >> 1) << 3);
    const int b_row_off = ((lane >> 4) << 3) + (lane & 7);
    const int b_kcol8   = (((lane >> 3) & 1) << 3);

    #pragma unroll 1
    for (int c = 0; c < NCHUNK; c++) {
        const int s = c & 1;
        const uint32_t stg = sb + s * STG_B;

        // ---- hoisted stage work (targets stage s^1 / regs only) ----
        if (c + 1 < NCHUNK)
            stsA(smem, (s ^ 1) * STG_B, tid, pf);   // A(c+1)
        if (c + 2 < NCHUNK)
            ldgA(A, bm, (c + 2) * KC, tid, pf);     // A(c+2) -> regs

        // ---- compute chunk c from stage s: 4 k16-steps ----
        #pragma unroll
        for (int ks = 0; ks < 4; ks++) {
            uint32_t af[4][4], bh[2][4], bl[2][4];
            const int akb = (ks * 16 + a_kcol8) * 2;
            const int bkb = (ks * 16 + b_kcol8) * 2;
            #pragma unroll
            for (int i = 0; i < 4; i++) {
                const uint32_t ra =
                    stg + (wm + i * 16 + a_row_off) * ROWB + akb;
                ldsm_x4(af[i][0], af[i][1], af[i][2], af[i][3], ra);
            }
            #pragma unroll
            for (int jj = 0; jj < 2; jj++) {
                const uint32_t rb =
                    stg + (wn + jj * 16 + b_row_off) * ROWB + bkb;
                ldsm_x4(bh[jj][0], bh[jj][1], bh[jj][2], bh[jj][3],
                        rb + OFF_BHI);
                ldsm_x4(bl[jj][0], bl[jj][1], bl[jj][2], bl[jj][3],
                        rb + OFF_BLO);
            }
            // T1: Ahi*Bhi
            #pragma unroll
            for (int i = 0; i < 4; i++)
                #pragma unroll
                for (int j = 0; j < 4; j++)
                    mma16816(acc[i][j], af[i], &bh[j >> 1][(j & 1) * 2]);
            // T2: Ahi*Blo
            #pragma unroll
            for (int i = 0; i < 4; i++)
                #pragma unroll
                for (int j = 0; j < 4; j++)
                    mma16816(acc[i][j], af[i], &bl[j >> 1][(j & 1) * 2]);
            // A lo (overwrite), T3: Alo*Bhi
            #pragma unroll
            for (int i = 0; i < 4; i++) {
                const uint32_t ra =
                    stg + (wm + i * 16 + a_row_off) * ROWB + akb;
                ldsm_x4(af[i][0], af[i][1], af[i][2], af[i][3],
                        ra + OFF_ALO);
            }
            #pragma unroll
            for (int i = 0; i < 4; i++)
                #pragma unroll
                for (int j = 0; j < 4; j++)
                    mma16816(acc[i][j], af[i], &bh[j >> 1][(j & 1) * 2]);
        }

        // ---- minimal tail ----
        CP_WAIT0();           // B(c+1) landed
        __syncthreads();      // stage s readers done; A(c+1)/B(c+1) visible
        if (c + 2 < NCHUNK) {
            cpB(stg, Whi, Wlo, bn, (c + 2) * KC, tid);  // into stage s
            CP_COMMIT();
        }
    }

    // epilogue
    #pragma unroll
    for (int i = 0; i < 4; i++) {
        const int r0 = bm + wm + i * 16 + (lane >> 2);
        #pragma unroll
        for (int j = 0; j < 4; j++) {
            const int c0 = bn + wn + j * 8 + ((lane & 3) << 1);
            const float b0 = bias[c0], b1 = bias[c0 + 1];
            float2 v0 = make_float2(acc[i][j][0] + b0, acc[i][j][1] + b1);
            float2 v1 = make_float2(acc[i][j][2] + b0, acc[i][j][3] + b1);
            *(float2*)(C + (size_t)r0 * DMODEL + c0) = v0;
            *(float2*)(C + (size_t)(r0 + 8) * DMODEL + c0) = v1;
        }
    }
}

// ---------------------------------------------------------------------------
// Attention core v3 (unchanged): one block per (s, h), 128 threads.
// ---------------------------------------------------------------------------
#define AT_SMEM (4 * 64 * 64 * 4)   // 65536
#define IDX(r, g) (((r) << 4) + ((((g) + ((r) >> 3)) & 15)))

__global__ void __launch_bounds__(128) attn3_kernel(
    const float* __restrict__ q, const float* __restrict__ k,
    const float* __restrict__ v, const int* __restrict__ mask,
    float* __restrict__ out)
{
    extern __shared__ float smf[];
    float4* Qs = (float4*)smf;
    float4* Ks = Qs + 1024;
    float4* Vs = Qs + 2048;
    float4* Ss = Qs + 3072;
    __shared__ float s_mv;

    const int s = blockIdx.x;
    const int h = blockIdx.y;
    const int tid = threadIdx.x;
    const int tx = tid & 7;
    const int ty = tid >> 3;
    const size_t base = ((size_t)s * BSZ) * DMODEL + (size_t)h * DKH;

    #pragma unroll
    for (int p = 0; p < 8; p++) {
        const int i = p * 128 + tid;
        const int b = i >> 4;
        const int g = i & 15;
        const size_t gm = base + (size_t)b * DMODEL + g * 4;
        Qs[IDX(b, g)] = *(const float4*)(q + gm);
        Ks[IDX(b, g)] = *(const float4*)(k + gm);
        Vs[IDX(b, g)] = *(const float4*)(v + gm);
    }
    if (tid < 32) {
        int a = 0;
        #pragma unroll
        for (int b = tid; b < 64; b += 32) {
            const int m = mask[b * SLEN + s];
            a += m * m;
        }
        #pragma unroll
        for (int o2 = 16; o2 > 0; o2 >>= 1)
            a += __shfl_xor_sync(0xffffffffu, a, o2);
        if (tid == 0) s_mv = (float)a;
    }
    __syncthreads();
    const bool masked = (s_mv == 0.0f);

    {
        float acc[4][8];
        #pragma unroll
        for (int i = 0; i < 4; i++)
            #pragma unroll
            for (int j = 0; j < 8; j++) acc[i][j] = 0.0f;

        #pragma unroll 2
        for (int g = 0; g < 16; g++) {
            float4 qr[4], kr[8];
            #pragma unroll
            for (int i = 0; i < 4; i++) qr[i] = Qs[IDX(ty * 4 + i, g)];
            #pragma unroll
            for (int j = 0; j < 8; j++) kr[j] = Ks[IDX(tx * 8 + j, g)];
            #pragma unroll
            for (int i = 0; i < 4; i++)
                #pragma unroll
                for (int j = 0; j < 8; j++) {
                    acc[i][j] += qr[i].x * kr[j].x + qr[i].y * kr[j].y
                               + qr[i].z * kr[j].z + qr[i].w * kr[j].w;
                }
        }
        #pragma unroll
        for (int i = 0; i < 4; i++) {
            float4 v0, v1;
            if (masked) {
                v0 = make_float4(-1e9f, -1e9f, -1e9f, -1e9f);
                v1 = v0;
            } else {
                v0 = make_float4(acc[i][0] * 0.125f, acc[i][1] * 0.125f,
                                 acc[i][2] * 0.125f, acc[i][3] * 0.125f);
                v1 = make_float4(acc[i][4] * 0.125f, acc[i][5] * 0.125f,
                                 acc[i][6] * 0.125f, acc[i][7] * 0.125f);
            }
            Ss[IDX(ty * 4 + i, tx * 2)]     = v0;
            Ss[IDX(ty * 4 + i, tx * 2 + 1)] = v1;
        }
    }
    __syncthreads();

    {
        float acc[4][8];
        #pragma unroll
        for (int i = 0; i < 4; i++)
            #pragma unroll
            for (int j = 0; j < 8; j++) acc[i][j] = 0.0f;

        #pragma unroll 2
        for (int g = 0; g < 16; g++) {
            float4 sr[4];
            #pragma unroll
            for (int i = 0; i < 4; i++) sr[i] = Ss[IDX(ty * 4 + i, g)];
            #pragma unroll
            for (int cc = 0; cc < 4; cc++) {
                const float4 vA = Vs[IDX(g * 4 + cc, tx * 2)];
                const float4 vB = Vs[IDX(g * 4 + cc, tx * 2 + 1)];
                #pragma unroll
                for (int i = 0; i < 4; i++) {
                    const float sv = (cc == 0) ? sr[i].x :
                                     (cc == 1) ? sr[i].y :
                                     (cc == 2) ? sr[i].z : sr[i].w;
                    acc[i][0] += sv * vA.x; acc[i][1] += sv * vA.y;
                    acc[i][2] += sv * vA.z; acc[i][3] += sv * vA.w;
                    acc[i][4] += sv * vB.x; acc[i][5] += sv * vB.y;
                    acc[i][6] += sv * vB.z; acc[i][7] += sv * vB.w;
                }
            }
        }
        #pragma unroll
        for (int i = 0; i < 4; i++) {
            Qs[IDX(ty * 4 + i, tx * 2)] =
                make_float4(acc[i][0], acc[i][1], acc[i][2], acc[i][3]);
            Qs[IDX(ty * 4 + i, tx * 2 + 1)] =
                make_float4(acc[i][4], acc[i][5], acc[i][6], acc[i][7]);
        }
    }
    __syncthreads();

    {
        const int lane = tid & 31;
        const int w = tid >> 5;
        const float* Qf = (const float*)Qs;
        for (int b = w; b < 64; b += 4) {
            const int c0 = lane, c1 = lane + 32;
            const float x0 = Qf[IDX(b, c0 >> 2) * 4 + (c0 & 3)];
            const float x1 = Qf[IDX(b, c1 >> 2) * 4 + (c1 & 3)];
            float mx = fmaxf(x0, x1);
            #pragma unroll
            for (int o2 = 16; o2 > 0; o2 >>= 1)
                mx = fmaxf(mx, __shfl_xor_sync(0xffffffffu, mx, o2));
            const float e0 = __expf(x0 - mx);
            const float e1 = __expf(x1 - mx);
            float sum = e0 + e1;
            #pragma unroll
            for (int o2 = 16; o2 > 0; o2 >>= 1)
                sum += __shfl_xor_sync(0xffffffffu, sum, o2);
            const float inv = 1.0f / sum;
            const size_t og = base + (size_t)b * DMODEL;
            out[og + c0] = e0 * inv;
            out[og + c1] = e1 * inv;
        }
    }
}

// ---------------------------------------------------------------------------
// Launch
// ---------------------------------------------------------------------------
extern "C" void kernel_launch(void* const* d_in, const int* in_sizes, int n_in,
                              void* d_out, int out_size)
{
    const float* K_in = (const float*)d_in[0];
    const float* V_in = (const float*)d_in[1];
    const int*   msk  = (const int*)d_in[2];
    const float* GT   = (const float*)d_in[3];
    const float* Wq   = (const float*)d_in[4];
    const float* bq   = (const float*)d_in[5];
    const float* Wk   = (const float*)d_in[6];
    const float* bk   = (const float*)d_in[7];
    const float* Wv   = (const float*)d_in[8];
    const float* bv   = (const float*)d_in[9];
    const float* Wo   = (const float*)d_in[10];
    const float* bo   = (const float*)d_in[11];
    float* out = (float*)d_out;

    float *gq, *gk, *gv, *gc;
    __half *whi, *wlo;
    cudaGetSymbolAddress((void**)&gq, g_q);
    cudaGetSymbolAddress((void**)&gk, g_k);
    cudaGetSymbolAddress((void**)&gv, g_v);
    cudaGetSymbolAddress((void**)&gc, g_c);
    cudaGetSymbolAddress((void**)&whi, g_whi);
    cudaGetSymbolAddress((void**)&wlo, g_wlo);

    cudaFuncSetAttribute(attn3_kernel,
                         cudaFuncAttributeMaxDynamicSharedMemorySize, AT_SMEM);
    cudaFuncSetAttribute(gemm_v7,
                         cudaFuncAttributeMaxDynamicSharedMemorySize, GEMM_SMEM);

    dim3 sg(1024, 4), sbk(256);
    split_all<<<sg, sbk>>>(Wq, Wk, Wv, Wo, whi, wlo);

    // batched Q/K/V projections in one launch
    GemmBatch bq3;
    bq3.A[0] = GT;   bq3.bias[0] = bq; bq3.C[0] = gq; bq3.widx[0] = 0;
    bq3.A[1] = K_in; bq3.bias[1] = bk; bq3.C[1] = gk; bq3.widx[1] = 1;
    bq3.A[2] = V_in; bq3.bias[2] = bv; bq3.C[2] = gv; bq3.widx[2] = 2;
    bq3.Whi = whi; bq3.Wlo = wlo;
    dim3 gg3(DMODEL / 256, M_TOT / 128, 3);   // (4, 512, 3)
    gemm_v7<<<gg3, GT_THR, GEMM_SMEM>>>(bq3);

    attn3_kernel<<<dim3(SLEN, NH), 128, AT_SMEM>>>(gq, gk, gv, msk, gc);

    // output projection
    GemmBatch bo1;
    bo1.A[0] = gc; bo1.bias[0] = bo; bo1.C[0] = out; bo1.widx[0] = 3;
    bo1.A[1] = gc; bo1.bias[1] = bo; bo1.C[1] = out; bo1.widx[1] = 3;
    bo1.A[2] = gc; bo1.bias[2] = bo; bo1.C[2] = out; bo1.widx[2] = 3;
    bo1.Whi = whi; bo1.Wlo = wlo;
    dim3 gg1(DMODEL / 256, M_TOT / 128, 1);   // (4, 512, 1)
    gemm_v7<<<gg1, GT_THR, GEMM_SMEM>>>(bo1);
}

// round 13
// speedup vs baseline: 1.0554x; 1.0554x over previous
#include <cuda_runtime.h>
#include <cuda_fp16.h>
#include <cstdint>

// Problem constants
#define SLEN 1024
#define BSZ  64
#define DMODEL 1024
#define NH   16
#define DKH  64
#define M_TOT (SLEN * BSZ)   // 65536

// Scratch
__device__ float g_q[67108864];
__device__ float g_k[67108864];
__device__ float g_v[67108864];
__device__ float g_c[67108864];
__device__ __half g_whi[4 * 1048576];   // 4 weights, hi
__device__ __half g_wlo[4 * 1048576];   // 4 weights, lo

// ---------------------------------------------------------------------------
// PTX helpers
// ---------------------------------------------------------------------------
__device__ __forceinline__ uint32_t smem_u32(const void* p) {
    uint32_t a;
    asm("{ .reg .u64 t; cvta.to.shared.u64 t, %1; cvt.u32.u64 %0, t; }"
        : "=r"(a) : "l"(p));
    return a;
}
__device__ __forceinline__ void cp16(uint32_t dst, const void* src) {
    asm volatile("cp.async.cg.shared.global [%0], [%1], 16;"
                 :: "r"(dst), "l"(src));
}
#define CP_COMMIT() asm volatile("cp.async.commit_group;" ::: "memory")
#define CP_WAIT1()  asm volatile("cp.async.wait_group 1;" ::: "memory")
#define CP_WAIT0()  asm volatile("cp.async.wait_group 0;" ::: "memory")

__device__ __forceinline__ void ldsm_x4(uint32_t& r0, uint32_t& r1,
                                        uint32_t& r2, uint32_t& r3, uint32_t a) {
    asm volatile("ldmatrix.sync.aligned.m8n8.x4.shared.b16 {%0,%1,%2,%3}, [%4];"
                 : "=r"(r0), "=r"(r1), "=r"(r2), "=r"(r3) : "r"(a));
}
__device__ __forceinline__ void mma16816(float* d, const uint32_t* a,
                                         const uint32_t* b) {
    asm volatile(
        "mma.sync.aligned.m16n8k16.row.col.f32.f16.f16.f32 "
        "{%0,%1,%2,%3}, {%4,%5,%6,%7}, {%8,%9}, {%0,%1,%2,%3};"
        : "+f"(d[0]), "+f"(d[1]), "+f"(d[2]), "+f"(d[3])
        : "r"(a[0]), "r"(a[1]), "r"(a[2]), "r"(a[3]), "r"(b[0]), "r"(b[1]));
}

// ---------------------------------------------------------------------------
// All-weights split fp32 -> (hi, lo) fp16, one launch. blockIdx.y = weight.
// ---------------------------------------------------------------------------
__global__ void __launch_bounds__(256) split_all(
    const float* __restrict__ w0, const float* __restrict__ w1,
    const float* __restrict__ w2, const float* __restrict__ w3,
    __half* __restrict__ hi, __half* __restrict__ lo)
{
    const int wsel = blockIdx.y;
    const float* in = (wsel == 0) ? w0 : (wsel == 1) ? w1 :
                      (wsel == 2) ? w2 : w3;
    const int i = blockIdx.x * blockDim.x + threadIdx.x;   // 0..262143
    const float4 v = ((const float4*)in)[i];
    __half h0 = __float2half_rn(v.x);
    __half h1 = __float2half_rn(v.y);
    __half h2 = __float2half_rn(v.z);
    __half h3 = __float2half_rn(v.w);
    __half l0 = __float2half_rn(v.x - __half2float(h0));
    __half l1 = __float2half_rn(v.y - __half2float(h1));
    __half l2 = __float2half_rn(v.z - __half2float(h2));
    __half l3 = __float2half_rn(v.w - __half2float(h3));
    const size_t o = (size_t)wsel * 1048576 + (size_t)i * 4;
    __half2* hp = (__half2*)(hi + o);
    __half2* lp = (__half2*)(lo + o);
    hp[0] = __halves2half2(h0, h1);
    hp[1] = __halves2half2(h2, h3);
    lp[0] = __halves2half2(l0, l1);
    lp[1] = __halves2half2(l2, l3);
}

// ---------------------------------------------------------------------------
// fp16-split GEMM v8 = v4 config (2 CTA/SM) + anti-phase stagger.
// CTA tile 128x128, 8 warps (2m x 4n), warp tile 64x32, 256 threads,
// 2 CTAs/SM (80KB smem each). Odd co-resident CTAs delay ~half a chunk
// period once, so their barrier tails overlap the partner's HMMA bursts.
// acc += Ahi*Whi + Ahi*Wlo + Alo*Whi  (fp32 accumulate).
// ---------------------------------------------------------------------------
#define LDH 40                            // halves per smem row (80B stride)
#define A_TILE_B (128 * LDH * 2)          // 10240
#define OFF_ALO  (A_TILE_B)
#define OFF_BHI  (2 * A_TILE_B)
#define OFF_BLO  (3 * A_TILE_B)
#define STG_B    (4 * A_TILE_B)           // 40960
#define GEMM_SMEM (2 * STG_B)             // 81920
#define NCHUNK 32
#define GT_THR 256
#define STAGGER_CYC 2200ull

__device__ __forceinline__ void ldgA(const float* __restrict__ A,
                                     int bm, int k0, int tid, float4* pf)
{
    #pragma unroll
    for (int p = 0; p < 4; p++) {
        const int idx = p * GT_THR + tid;   // 0..1023
        const int row = idx >> 3;
        const int q   = idx & 7;
        pf[p] = *(const float4*)(A + (size_t)(bm + row) * DMODEL + k0 + q * 4);
    }
}

__device__ __forceinline__ void stsA(char* smem_base, int stg_off,
                                     int tid, const float4* pf)
{
    #pragma unroll
    for (int p = 0; p < 4; p++) {
        const int idx = p * GT_THR + tid;
        const int row = idx >> 3;
        const int q   = idx & 7;
        const float4 v = pf[p];
        __half2 h01 = __floats2half2_rn(v.x, v.y);
        __half2 h23 = __floats2half2_rn(v.z, v.w);
        __half2 l01 = __floats2half2_rn(v.x - __low2float(h01),
                                        v.y - __high2float(h01));
        __half2 l23 = __floats2half2_rn(v.z - __low2float(h23),
                                        v.w - __high2float(h23));
        char* d = smem_base + stg_off + row * (LDH * 2) + q * 8;
        *(__half2*)(d)               = h01;
        *(__half2*)(d + 4)           = h23;
        *(__half2*)(d + OFF_ALO)     = l01;
        *(__half2*)(d + OFF_ALO + 4) = l23;
    }
}

__device__ __forceinline__ void cpB(uint32_t stg, const __half* __restrict__ Whi,
                                    const __half* __restrict__ Wlo,
                                    int bn, int k0, int tid)
{
    #pragma unroll
    for (int p = 0; p < 2; p++) {
        const int idx = p * GT_THR + tid;   // 0..511
        const int row = idx >> 2;           // 0..127
        const int qq  = idx & 3;
        const uint32_t d = stg + OFF_BHI + row * (LDH * 2) + qq * 16;
        const size_t g = (size_t)(bn + row) * DMODEL + k0 + qq * 8;
        cp16(d, Whi + g);
        cp16(d + (OFF_BLO - OFF_BHI), Wlo + g);
    }
}

__global__ void __launch_bounds__(GT_THR, 2) gemm_v8(
    const float* __restrict__ A, const __half* __restrict__ Whi,
    const __half* __restrict__ Wlo, const float* __restrict__ bias,
    float* __restrict__ C)
{
    extern __shared__ char smem[];
    const uint32_t sb = smem_u32(smem);
    const int tid = threadIdx.x;
    const int lane = tid & 31;
    const int wid = tid >> 5;
    const int bm = blockIdx.y * 128;
    const int bn = blockIdx.x * 128;
    const int wm = (wid & 1) * 64;
    const int wn = (wid >> 1) * 32;

    // Anti-phase stagger: co-resident CTAs (wave layers of 148) alternate.
    {
        const int bid = blockIdx.x + blockIdx.y * gridDim.x;
        if ((bid / 148) & 1) {
            const unsigned long long t0 = clock64();
            while (clock64() - t0 < STAGGER_CYC) { }
        }
    }

    float acc[4][4][4];
    #pragma unroll
    for (int i = 0; i < 4; i++)
        #pragma unroll
        for (int j = 0; j < 4; j++)
            #pragma unroll
            for (int x = 0; x < 4; x++) acc[i][j][x] = 0.0f;

    float4 pf[4];

    // prologue: A(0) into stage0, B(0)/B(1) in flight, pf <- A(1)
    ldgA(A, bm, 0, tid, pf);
    stsA(smem, 0, tid, pf);
    cpB(sb, Whi, Wlo, bn, 0, tid);
    CP_COMMIT();
    ldgA(A, bm, 32, tid, pf);
    cpB(sb + STG_B, Whi, Wlo, bn, 32, tid);
    CP_COMMIT();
    CP_WAIT1();
    __syncthreads();

    // fragment address components
    const int at = lane >> 3, ar = lane & 7;
    const int a_row_off = ((at & 1) << 3) + ar;
    const int a_kcol8   = ((at >> 1) << 3);
    const int b_row_off = ((lane >> 4) << 3) + (lane & 7);
    const int b_kcol8   = (((lane >> 3) & 1) << 3);

    #pragma unroll 1
    for (int c = 0; c < NCHUNK; c++) {
        const int s = c & 1;
        const uint32_t stg = sb + s * STG_B;

        // ---- hoisted stage work (targets stage s^1 / regs only) ----
        if (c + 1 < NCHUNK)
            stsA(smem, (s ^ 1) * STG_B, tid, pf);   // A(c+1)
        if (c + 2 < NCHUNK)
            ldgA(A, bm, (c + 2) * 32, tid, pf);     // A(c+2) -> regs

        // ---- compute chunk c from stage s ----
        #pragma unroll
        for (int ks = 0; ks < 2; ks++) {
            uint32_t af[4][4], bh[2][4], bl[2][4];
            const int akb = (ks * 16 + a_kcol8) * 2;
            const int bkb = (ks * 16 + b_kcol8) * 2;
            #pragma unroll
            for (int i = 0; i < 4; i++) {
                const uint32_t ra =
                    stg + (wm + i * 16 + a_row_off) * (LDH * 2) + akb;
                ldsm_x4(af[i][0], af[i][1], af[i][2], af[i][3], ra);
            }
            #pragma unroll
            for (int jj = 0; jj < 2; jj++) {
                const uint32_t rb =
                    stg + (wn + jj * 16 + b_row_off) * (LDH * 2) + bkb;
                ldsm_x4(bh[jj][0], bh[jj][1], bh[jj][2], bh[jj][3],
                        rb + OFF_BHI);
                ldsm_x4(bl[jj][0], bl[jj][1], bl[jj][2], bl[jj][3],
                        rb + OFF_BLO);
            }
            #pragma unroll
            for (int i = 0; i < 4; i++)
                #pragma unroll
                for (int j = 0; j < 4; j++)
                    mma16816(acc[i][j], af[i], &bh[j >> 1][(j & 1) * 2]);
            #pragma unroll
            for (int i = 0; i < 4; i++)
                #pragma unroll
                for (int j = 0; j < 4; j++)
                    mma16816(acc[i][j], af[i], &bl[j >> 1][(j & 1) * 2]);
            #pragma unroll
            for (int i = 0; i < 4; i++) {
                const uint32_t ra =
                    stg + (wm + i * 16 + a_row_off) * (LDH * 2) + akb;
                ldsm_x4(af[i][0], af[i][1], af[i][2], af[i][3],
                        ra + OFF_ALO);
            }
            #pragma unroll
            for (int i = 0; i < 4; i++)
                #pragma unroll
                for (int j = 0; j < 4; j++)
                    mma16816(acc[i][j], af[i], &bh[j >> 1][(j & 1) * 2]);
        }

        // ---- minimal tail ----
        CP_WAIT0();           // B(c+1) landed
        __syncthreads();      // stage s readers done; A(c+1)/B(c+1) visible
        if (c + 2 < NCHUNK) {
            cpB(stg, Whi, Wlo, bn, (c + 2) * 32, tid);  // into stage s
            CP_COMMIT();
        }
    }

    // epilogue
    #pragma unroll
    for (int i = 0; i < 4; i++) {
        const int r0 = bm + wm + i * 16 + (lane >> 2);
        #pragma unroll
        for (int j = 0; j < 4; j++) {
            const int c0 = bn + wn + j * 8 + ((lane & 3) << 1);
            const float b0 = bias[c0], b1 = bias[c0 + 1];
            float2 v0 = make_float2(acc[i][j][0] + b0, acc[i][j][1] + b1);
            float2 v1 = make_float2(acc[i][j][2] + b0, acc[i][j][3] + b1);
            *(float2*)(C + (size_t)r0 * DMODEL + c0) = v0;
            *(float2*)(C + (size_t)(r0 + 8) * DMODEL + c0) = v1;
        }
    }
}

// ---------------------------------------------------------------------------
// Attention core v3 (unchanged, measured-good): one block per (s, h).
// ---------------------------------------------------------------------------
#define AT_SMEM (4 * 64 * 64 * 4)   // 65536
#define IDX(r, g) (((r) << 4) + ((((g) + ((r) >> 3)) & 15)))

__global__ void __launch_bounds__(128) attn3_kernel(
    const float* __restrict__ q, const float* __restrict__ k,
    const float* __restrict__ v, const int* __restrict__ mask,
    float* __restrict__ out)
{
    extern __shared__ float smf[];
    float4* Qs = (float4*)smf;
    float4* Ks = Qs + 1024;
    float4* Vs = Qs + 2048;
    float4* Ss = Qs + 3072;
    __shared__ float s_mv;

    const int s = blockIdx.x;
    const int h = blockIdx.y;
    const int tid = threadIdx.x;
    const int tx = tid & 7;
    const int ty = tid >> 3;
    const size_t base = ((size_t)s * BSZ) * DMODEL + (size_t)h * DKH;

    #pragma unroll
    for (int p = 0; p < 8; p++) {
        const int i = p * 128 + tid;
        const int b = i >> 4;
        const int g = i & 15;
        const size_t gm = base + (size_t)b * DMODEL + g * 4;
        Qs[IDX(b, g)] = *(const float4*)(q + gm);
        Ks[IDX(b, g)] = *(const float4*)(k + gm);
        Vs[IDX(b, g)] = *(const float4*)(v + gm);
    }
    if (tid < 32) {
        int a = 0;
        #pragma unroll
        for (int b = tid; b < 64; b += 32) {
            const int m = mask[b * SLEN + s];
            a += m * m;
        }
        #pragma unroll
        for (int o2 = 16; o2 > 0; o2 >>= 1)
            a += __shfl_xor_sync(0xffffffffu, a, o2);
        if (tid == 0) s_mv = (float)a;
    }
    __syncthreads();
    const bool masked = (s_mv == 0.0f);

    {
        float acc[4][8];
        #pragma unroll
        for (int i = 0; i < 4; i++)
            #pragma unroll
            for (int j = 0; j < 8; j++) acc[i][j] = 0.0f;

        #pragma unroll 2
        for (int g = 0; g < 16; g++) {
            float4 qr[4], kr[8];
            #pragma unroll
            for (int i = 0; i < 4; i++) qr[i] = Qs[IDX(ty * 4 + i, g)];
            #pragma unroll
            for (int j = 0; j < 8; j++) kr[j] = Ks[IDX(tx * 8 + j, g)];
            #pragma unroll
            for (int i = 0; i < 4; i++)
                #pragma unroll
                for (int j = 0; j < 8; j++) {
                    acc[i][j] += qr[i].x * kr[j].x + qr[i].y * kr[j].y
                               + qr[i].z * kr[j].z + qr[i].w * kr[j].w;
                }
        }
        #pragma unroll
        for (int i = 0; i < 4; i++) {
            float4 v0, v1;
            if (masked) {
                v0 = make_float4(-1e9f, -1e9f, -1e9f, -1e9f);
                v1 = v0;
            } else {
                v0 = make_float4(acc[i][0] * 0.125f, acc[i][1] * 0.125f,
                                 acc[i][2] * 0.125f, acc[i][3] * 0.125f);
                v1 = make_float4(acc[i][4] * 0.125f, acc[i][5] * 0.125f,
                                 acc[i][6] * 0.125f, acc[i][7] * 0.125f);
            }
            Ss[IDX(ty * 4 + i, tx * 2)]     = v0;
            Ss[IDX(ty * 4 + i, tx * 2 + 1)] = v1;
        }
    }
    __syncthreads();

    {
        float acc[4][8];
        #pragma unroll
        for (int i = 0; i < 4; i++)
            #pragma unroll
            for (int j = 0; j < 8; j++) acc[i][j] = 0.0f;

        #pragma unroll 2
        for (int g = 0; g < 16; g++) {
            float4 sr[4];
            #pragma unroll
            for (int i = 0; i < 4; i++) sr[i] = Ss[IDX(ty * 4 + i, g)];
            #pragma unroll
            for (int cc = 0; cc < 4; cc++) {
                const float4 vA = Vs[IDX(g * 4 + cc, tx * 2)];
                const float4 vB = Vs[IDX(g * 4 + cc, tx * 2 + 1)];
                #pragma unroll
                for (int i = 0; i < 4; i++) {
                    const float sv = (cc == 0) ? sr[i].x :
                                     (cc == 1) ? sr[i].y :
                                     (cc == 2) ? sr[i].z : sr[i].w;
                    acc[i][0] += sv * vA.x; acc[i][1] += sv * vA.y;
                    acc[i][2] += sv * vA.z; acc[i][3] += sv * vA.w;
                    acc[i][4] += sv * vB.x; acc[i][5] += sv * vB.y;
                    acc[i][6] += sv * vB.z; acc[i][7] += sv * vB.w;
                }
            }
        }
        #pragma unroll
        for (int i = 0; i < 4; i++) {
            Qs[IDX(ty * 4 + i, tx * 2)] =
                make_float4(acc[i][0], acc[i][1], acc[i][2], acc[i][3]);
            Qs[IDX(ty * 4 + i, tx * 2 + 1)] =
                make_float4(acc[i][4], acc[i][5], acc[i][6], acc[i][7]);
        }
    }
    __syncthreads();

    {
        const int lane = tid & 31;
        const int w = tid >> 5;
        const float* Qf = (const float*)Qs;
        for (int b = w; b < 64; b += 4) {
            const int c0 = lane, c1 = lane + 32;
            const float x0 = Qf[IDX(b, c0 >> 2) * 4 + (c0 & 3)];
            const float x1 = Qf[IDX(b, c1 >> 2) * 4 + (c1 & 3)];
            float mx = fmaxf(x0, x1);
            #pragma unroll
            for (int o2 = 16; o2 > 0; o2 >>= 1)
                mx = fmaxf(mx, __shfl_xor_sync(0xffffffffu, mx, o2));
            const float e0 = __expf(x0 - mx);
            const float e1 = __expf(x1 - mx);
            float sum = e0 + e1;
            #pragma unroll
            for (int o2 = 16; o2 > 0; o2 >>= 1)
                sum += __shfl_xor_sync(0xffffffffu, sum, o2);
            const float inv = 1.0f / sum;
            const size_t og = base + (size_t)b * DMODEL;
            out[og + c0] = e0 * inv;
            out[og + c1] = e1 * inv;
        }
    }
}

// ---------------------------------------------------------------------------
// Launch
// ---------------------------------------------------------------------------
extern "C" void kernel_launch(void* const* d_in, const int* in_sizes, int n_in,
                              void* d_out, int out_size)
{
    const float* K_in = (const float*)d_in[0];
    const float* V_in = (const float*)d_in[1];
    const int*   msk  = (const int*)d_in[2];
    const float* GT   = (const float*)d_in[3];
    const float* Wq   = (const float*)d_in[4];
    const float* bq   = (const float*)d_in[5];
    const float* Wk   = (const float*)d_in[6];
    const float* bk   = (const float*)d_in[7];
    const float* Wv   = (const float*)d_in[8];
    const float* bv   = (const float*)d_in[9];
    const float* Wo   = (const float*)d_in[10];
    const float* bo   = (const float*)d_in[11];
    float* out = (float*)d_out;

    float *gq, *gk, *gv, *gc;
    __half *whi, *wlo;
    cudaGetSymbolAddress((void**)&gq, g_q);
    cudaGetSymbolAddress((void**)&gk, g_k);
    cudaGetSymbolAddress((void**)&gv, g_v);
    cudaGetSymbolAddress((void**)&gc, g_c);
    cudaGetSymbolAddress((void**)&whi, g_whi);
    cudaGetSymbolAddress((void**)&wlo, g_wlo);

    cudaFuncSetAttribute(attn3_kernel,
                         cudaFuncAttributeMaxDynamicSharedMemorySize, AT_SMEM);
    cudaFuncSetAttribute(gemm_v8,
                         cudaFuncAttributeMaxDynamicSharedMemorySize, GEMM_SMEM);

    dim3 sg(1024, 4), sbk(256);
    split_all<<<sg, sbk>>>(Wq, Wk, Wv, Wo, whi, wlo);

    dim3 gg(DMODEL / 128, M_TOT / 128);   // (8, 512)
    dim3 gb(GT_THR);

    gemm_v8<<<gg, gb, GEMM_SMEM>>>(GT,   whi,               wlo,               bq, gq);
    gemm_v8<<<gg, gb, GEMM_SMEM>>>(K_in, whi + 1048576,     wlo + 1048576,     bk, gk);
    gemm_v8<<<gg, gb, GEMM_SMEM>>>(V_in, whi + 2 * 1048576, wlo + 2 * 1048576, bv, gv);
    attn3_kernel<<<dim3(SLEN, NH), 128, AT_SMEM>>>(gq, gk, gv, msk, gc);
    gemm_v8<<<gg, gb, GEMM_SMEM>>>(gc, whi + 3 * 1048576, wlo + 3 * 1048576, bo, out);
}

// round 14
// speedup vs baseline: 1.0686x; 1.0125x over previous
#include <cuda_runtime.h>
#include <cuda_fp16.h>
#include <cstdint>

// Problem constants
#define SLEN 1024
#define BSZ  64
#define DMODEL 1024
#define NH   16
#define DKH  64
#define M_TOT (SLEN * BSZ)   // 65536

// Scratch
__device__ float g_q[67108864];
__device__ float g_k[67108864];
__device__ float g_v[67108864];
__device__ float g_c[67108864];
__device__ __half g_whi[4 * 1048576];   // 4 weights, hi
__device__ __half g_wlo[4 * 1048576];   // 4 weights, lo

// ---------------------------------------------------------------------------
// PTX helpers
// ---------------------------------------------------------------------------
__device__ __forceinline__ uint32_t smem_u32(const void* p) {
    uint32_t a;
    asm("{ .reg .u64 t; cvta.to.shared.u64 t, %1; cvt.u32.u64 %0, t; }"
        : "=r"(a) : "l"(p));
    return a;
}
__device__ __forceinline__ void cp16(uint32_t dst, const void* src) {
    asm volatile("cp.async.cg.shared.global [%0], [%1], 16;"
                 :: "r"(dst), "l"(src));
}
#define CP_COMMIT() asm volatile("cp.async.commit_group;" ::: "memory")
#define CP_WAIT1()  asm volatile("cp.async.wait_group 1;" ::: "memory")
#define CP_WAIT0()  asm volatile("cp.async.wait_group 0;" ::: "memory")

__device__ __forceinline__ void ldsm_x4(uint32_t& r0, uint32_t& r1,
                                        uint32_t& r2, uint32_t& r3, uint32_t a) {
    asm volatile("ldmatrix.sync.aligned.m8n8.x4.shared.b16 {%0,%1,%2,%3}, [%4];"
                 : "=r"(r0), "=r"(r1), "=r"(r2), "=r"(r3) : "r"(a));
}
__device__ __forceinline__ void mma16816(float* d, const uint32_t* a,
                                         const uint32_t* b) {
    asm volatile(
        "mma.sync.aligned.m16n8k16.row.col.f32.f16.f16.f32 "
        "{%0,%1,%2,%3}, {%4,%5,%6,%7}, {%8,%9}, {%0,%1,%2,%3};"
        : "+f"(d[0]), "+f"(d[1]), "+f"(d[2]), "+f"(d[3])
        : "r"(a[0]), "r"(a[1]), "r"(a[2]), "r"(a[3]), "r"(b[0]), "r"(b[1]));
}

// packed f32x2: 2 FMAs per issue (sm_100+ base PTX)
__device__ __forceinline__ uint64_t fma2(uint64_t a, uint64_t b, uint64_t c) {
    uint64_t d;
    asm("fma.rn.f32x2 %0, %1, %2, %3;" : "=l"(d) : "l"(a), "l"(b), "l"(c));
    return d;
}
__device__ __forceinline__ uint64_t bcast2(float s) {
    uint64_t d;
    const uint32_t b = __float_as_uint(s);
    asm("mov.b64 %0, {%1, %1};" : "=l"(d) : "r"(b));
    return d;
}
__device__ __forceinline__ float pairsum(uint64_t p) {
    return __uint_as_float((uint32_t)p) + __uint_as_float((uint32_t)(p >> 32));
}

// ---------------------------------------------------------------------------
// All-weights split fp32 -> (hi, lo) fp16, one launch. blockIdx.y = weight.
// ---------------------------------------------------------------------------
__global__ void __launch_bounds__(256) split_all(
    const float* __restrict__ w0, const float* __restrict__ w1,
    const float* __restrict__ w2, const float* __restrict__ w3,
    __half* __restrict__ hi, __half* __restrict__ lo)
{
    const int wsel = blockIdx.y;
    const float* in = (wsel == 0) ? w0 : (wsel == 1) ? w1 :
                      (wsel == 2) ? w2 : w3;
    const int i = blockIdx.x * blockDim.x + threadIdx.x;   // 0..262143
    const float4 v = ((const float4*)in)[i];
    __half h0 = __float2half_rn(v.x);
    __half h1 = __float2half_rn(v.y);
    __half h2 = __float2half_rn(v.z);
    __half h3 = __float2half_rn(v.w);
    __half l0 = __float2half_rn(v.x - __half2float(h0));
    __half l1 = __float2half_rn(v.y - __half2float(h1));
    __half l2 = __float2half_rn(v.z - __half2float(h2));
    __half l3 = __float2half_rn(v.w - __half2float(h3));
    const size_t o = (size_t)wsel * 1048576 + (size_t)i * 4;
    __half2* hp = (__half2*)(hi + o);
    __half2* lp = (__half2*)(lo + o);
    hp[0] = __halves2half2(h0, h1);
    hp[1] = __halves2half2(h2, h3);
    lp[0] = __halves2half2(l0, l1);
    lp[1] = __halves2half2(l2, l3);
}

// ---------------------------------------------------------------------------
// fp16-split GEMM v5 (R8 config, best measured): CTA 128x256, 16 warps
// (2m x 8n), warp tile 64x32, KC=64 (16 chunks), 2 stages x 108KB, 1 CTA/SM.
// acc += Ahi*Whi + Ahi*Wlo + Alo*Whi  (fp32 accumulate).
// ---------------------------------------------------------------------------
#define KC 64
#define LDH 72
#define ROWB (LDH * 2)                    // 144
#define A_TILE_B (128 * ROWB)             // 18432
#define B_TILE_B (256 * ROWB)             // 36864
#define OFF_ALO  (A_TILE_B)
#define OFF_BHI  (2 * A_TILE_B)
#define OFF_BLO  (2 * A_TILE_B + B_TILE_B)
#define STG_B    (2 * A_TILE_B + 2 * B_TILE_B)   // 110592
#define GEMM_SMEM (2 * STG_B)                    // 221184
#define NCHUNK 16
#define GT_THR 512

__device__ __forceinline__ void ldgA(const float* __restrict__ A,
                                     int bm, int k0, int tid, float4* pf)
{
    #pragma unroll
    for (int p = 0; p < 4; p++) {
        const int idx = p * GT_THR + tid;
        const int row = idx >> 4;
        const int q   = idx & 15;
        pf[p] = *(const float4*)(A + (size_t)(bm + row) * DMODEL + k0 + q * 4);
    }
}

__device__ __forceinline__ void stsA(char* smem_base, int stg_off,
                                     int tid, const float4* pf)
{
    #pragma unroll
    for (int p = 0; p < 4; p++) {
        const int idx = p * GT_THR + tid;
        const int row = idx >> 4;
        const int q   = idx & 15;
        const float4 v = pf[p];
        __half2 h01 = __floats2half2_rn(v.x, v.y);
        __half2 h23 = __floats2half2_rn(v.z, v.w);
        __half2 l01 = __floats2half2_rn(v.x - __low2float(h01),
                                        v.y - __high2float(h01));
        __half2 l23 = __floats2half2_rn(v.z - __low2float(h23),
                                        v.w - __high2float(h23));
        char* d = smem_base + stg_off + row * ROWB + q * 8;
        *(__half2*)(d)               = h01;
        *(__half2*)(d + 4)           = h23;
        *(__half2*)(d + OFF_ALO)     = l01;
        *(__half2*)(d + OFF_ALO + 4) = l23;
    }
}

__device__ __forceinline__ void cpB(uint32_t stg, const __half* __restrict__ Whi,
                                    const __half* __restrict__ Wlo,
                                    int bn, int k0, int tid)
{
    #pragma unroll
    for (int p = 0; p < 4; p++) {
        const int idx = p * GT_THR + tid;
        const int row = idx >> 3;
        const int qq  = idx & 7;
        const uint32_t d = stg + OFF_BHI + row * ROWB + qq * 16;
        const size_t g = (size_t)(bn + row) * DMODEL + k0 + qq * 8;
        cp16(d, Whi + g);
        cp16(d + (OFF_BLO - OFF_BHI), Wlo + g);
    }
}

__global__ void __launch_bounds__(GT_THR, 1) gemm_v5(
    const float* __restrict__ A, const __half* __restrict__ Whi,
    const __half* __restrict__ Wlo, const float* __restrict__ bias,
    float* __restrict__ C)
{
    extern __shared__ char smem[];
    const uint32_t sb = smem_u32(smem);
    const int tid = threadIdx.x;
    const int lane = tid & 31;
    const int wid = tid >> 5;
    const int bm = blockIdx.y * 128;
    const int bn = blockIdx.x * 256;
    const int wm = (wid & 1) * 64;
    const int wn = (wid >> 1) * 32;

    float acc[4][4][4];
    #pragma unroll
    for (int i = 0; i < 4; i++)
        #pragma unroll
        for (int j = 0; j < 4; j++)
            #pragma unroll
            for (int x = 0; x < 4; x++) acc[i][j][x] = 0.0f;

    float4 pf[4];

    ldgA(A, bm, 0, tid, pf);
    stsA(smem, 0, tid, pf);
    cpB(sb, Whi, Wlo, bn, 0, tid);
    CP_COMMIT();
    ldgA(A, bm, KC, tid, pf);
    cpB(sb + STG_B, Whi, Wlo, bn, KC, tid);
    CP_COMMIT();
    CP_WAIT1();
    __syncthreads();

    const int at = lane >> 3, ar = lane & 7;
    const int a_row_off = ((at & 1) << 3) + ar;
    const int a_kcol8   = ((at >> 1) << 3);
    const int b_row_off = ((lane >> 4) << 3) + (lane & 7);
    const int b_kcol8   = (((lane >> 3) & 1) << 3);

    #pragma unroll 1
    for (int c = 0; c < NCHUNK; c++) {
        const int s = c & 1;
        const uint32_t stg = sb + s * STG_B;

        if (c + 1 < NCHUNK)
            stsA(smem, (s ^ 1) * STG_B, tid, pf);
        if (c + 2 < NCHUNK)
            ldgA(A, bm, (c + 2) * KC, tid, pf);

        #pragma unroll
        for (int ks = 0; ks < 4; ks++) {
            uint32_t af[4][4], bh[2][4], bl[2][4];
            const int akb = (ks * 16 + a_kcol8) * 2;
            const int bkb = (ks * 16 + b_kcol8) * 2;
            #pragma unroll
            for (int i = 0; i < 4; i++) {
                const uint32_t ra =
                    stg + (wm + i * 16 + a_row_off) * ROWB + akb;
                ldsm_x4(af[i][0], af[i][1], af[i][2], af[i][3], ra);
            }
            #pragma unroll
            for (int jj = 0; jj < 2; jj++) {
                const uint32_t rb =
                    stg + (wn + jj * 16 + b_row_off) * ROWB + bkb;
                ldsm_x4(bh[jj][0], bh[jj][1], bh[jj][2], bh[jj][3],
                        rb + OFF_BHI);
                ldsm_x4(bl[jj][0], bl[jj][1], bl[jj][2], bl[jj][3],
                        rb + OFF_BLO);
            }
            #pragma unroll
            for (int i = 0; i < 4; i++)
                #pragma unroll
                for (int j = 0; j < 4; j++)
                    mma16816(acc[i][j], af[i], &bh[j >> 1][(j & 1) * 2]);
            #pragma unroll
            for (int i = 0; i < 4; i++)
                #pragma unroll
                for (int j = 0; j < 4; j++)
                    mma16816(acc[i][j], af[i], &bl[j >> 1][(j & 1) * 2]);
            #pragma unroll
            for (int i = 0; i < 4; i++) {
                const uint32_t ra =
                    stg + (wm + i * 16 + a_row_off) * ROWB + akb;
                ldsm_x4(af[i][0], af[i][1], af[i][2], af[i][3],
                        ra + OFF_ALO);
            }
            #pragma unroll
            for (int i = 0; i < 4; i++)
                #pragma unroll
                for (int j = 0; j < 4; j++)
                    mma16816(acc[i][j], af[i], &bh[j >> 1][(j & 1) * 2]);
        }

        CP_WAIT0();
        __syncthreads();
        if (c + 2 < NCHUNK) {
            cpB(stg, Whi, Wlo, bn, (c + 2) * KC, tid);
            CP_COMMIT();
        }
    }

    #pragma unroll
    for (int i = 0; i < 4; i++) {
        const int r0 = bm + wm + i * 16 + (lane >> 2);
        #pragma unroll
        for (int j = 0; j < 4; j++) {
            const int c0 = bn + wn + j * 8 + ((lane & 3) << 1);
            const float b0 = bias[c0], b1 = bias[c0 + 1];
            float2 v0 = make_float2(acc[i][j][0] + b0, acc[i][j][1] + b1);
            float2 v1 = make_float2(acc[i][j][2] + b0, acc[i][j][3] + b1);
            *(float2*)(C + (size_t)r0 * DMODEL + c0) = v0;
            *(float2*)(C + (size_t)(r0 + 8) * DMODEL + c0) = v1;
        }
    }
}

// ---------------------------------------------------------------------------
// Attention core v4: one block per (s, h), 128 threads, 4x8 tiles,
// packed fma.rn.f32x2 (2 FMAs/issue) in both GEMM phases.
// Swizzled smem: float4 slot IDX(r,g) = r*16 + ((g + (r>>3)) & 15).
// ---------------------------------------------------------------------------
#define AT_SMEM (4 * 64 * 64 * 4)   // 65536
#define IDX(r, g) (((r) << 4) + ((((g) + ((r) >> 3)) & 15)))

__global__ void __launch_bounds__(128) attn4_kernel(
    const float* __restrict__ q, const float* __restrict__ k,
    const float* __restrict__ v, const int* __restrict__ mask,
    float* __restrict__ out)
{
    extern __shared__ float smf[];
    float4* Qs = (float4*)smf;
    float4* Ks = Qs + 1024;
    float4* Vs = Qs + 2048;
    float4* Ss = Qs + 3072;
    __shared__ float s_mv;

    const int s = blockIdx.x;
    const int h = blockIdx.y;
    const int tid = threadIdx.x;
    const int tx = tid & 7;       // 8 col groups (8 cols each)
    const int ty = tid >> 3;      // 16 row groups (4 rows each)
    const size_t base = ((size_t)s * BSZ) * DMODEL + (size_t)h * DKH;

    #pragma unroll
    for (int p = 0; p < 8; p++) {
        const int i = p * 128 + tid;
        const int b = i >> 4;
        const int g = i & 15;
        const size_t gm = base + (size_t)b * DMODEL + g * 4;
        Qs[IDX(b, g)] = *(const float4*)(q + gm);
        Ks[IDX(b, g)] = *(const float4*)(k + gm);
        Vs[IDX(b, g)] = *(const float4*)(v + gm);
    }
    if (tid < 32) {
        int a = 0;
        #pragma unroll
        for (int b = tid; b < 64; b += 32) {
            const int m = mask[b * SLEN + s];
            a += m * m;
        }
        #pragma unroll
        for (int o2 = 16; o2 > 0; o2 >>= 1)
            a += __shfl_xor_sync(0xffffffffu, a, o2);
        if (tid == 0) s_mv = (float)a;
    }
    __syncthreads();
    const bool masked = (s_mv == 0.0f);

    // phase 1: scores = Q K^T / 8 (masked) -> Ss  [packed f32x2 dot products]
    {
        uint64_t acc2[4][8];
        #pragma unroll
        for (int i = 0; i < 4; i++)
            #pragma unroll
            for (int j = 0; j < 8; j++) acc2[i][j] = 0ull;

        #pragma unroll 2
        for (int g = 0; g < 16; g++) {
            ulonglong2 q2[4], k2[8];
            #pragma unroll
            for (int i = 0; i < 4; i++)
                q2[i] = *(const ulonglong2*)&Qs[IDX(ty * 4 + i, g)];
            #pragma unroll
            for (int j = 0; j < 8; j++)
                k2[j] = *(const ulonglong2*)&Ks[IDX(tx * 8 + j, g)];
            #pragma unroll
            for (int i = 0; i < 4; i++)
                #pragma unroll
                for (int j = 0; j < 8; j++) {
                    acc2[i][j] = fma2(q2[i].x, k2[j].x, acc2[i][j]);
                    acc2[i][j] = fma2(q2[i].y, k2[j].y, acc2[i][j]);
                }
        }
        #pragma unroll
        for (int i = 0; i < 4; i++) {
            float4 v0, v1;
            if (masked) {
                v0 = make_float4(-1e9f, -1e9f, -1e9f, -1e9f);
                v1 = v0;
            } else {
                v0 = make_float4(pairsum(acc2[i][0]) * 0.125f,
                                 pairsum(acc2[i][1]) * 0.125f,
                                 pairsum(acc2[i][2]) * 0.125f,
                                 pairsum(acc2[i][3]) * 0.125f);
                v1 = make_float4(pairsum(acc2[i][4]) * 0.125f,
                                 pairsum(acc2[i][5]) * 0.125f,
                                 pairsum(acc2[i][6]) * 0.125f,
                                 pairsum(acc2[i][7]) * 0.125f);
            }
            Ss[IDX(ty * 4 + i, tx * 2)]     = v0;
            Ss[IDX(ty * 4 + i, tx * 2 + 1)] = v1;
        }
    }
    __syncthreads();

    // phase 2: attn = scores @ V -> Qs  [packed broadcast-FMA]
    {
        uint64_t acc2[4][4];   // 4 packed pairs = 8 output cols per row
        #pragma unroll
        for (int i = 0; i < 4; i++)
            #pragma unroll
            for (int j = 0; j < 4; j++) acc2[i][j] = 0ull;

        #pragma unroll 2
        for (int g = 0; g < 16; g++) {
            float4 sr[4];
            #pragma unroll
            for (int i = 0; i < 4; i++) sr[i] = Ss[IDX(ty * 4 + i, g)];
            #pragma unroll
            for (int cc = 0; cc < 4; cc++) {
                const ulonglong2 vA =
                    *(const ulonglong2*)&Vs[IDX(g * 4 + cc, tx * 2)];
                const ulonglong2 vB =
                    *(const ulonglong2*)&Vs[IDX(g * 4 + cc, tx * 2 + 1)];
                #pragma unroll
                for (int i = 0; i < 4; i++) {
                    const float sv = (cc == 0) ? sr[i].x :
                                     (cc == 1) ? sr[i].y :
                                     (cc == 2) ? sr[i].z : sr[i].w;
                    const uint64_t svp = bcast2(sv);
                    acc2[i][0] = fma2(svp, vA.x, acc2[i][0]);
                    acc2[i][1] = fma2(svp, vA.y, acc2[i][1]);
                    acc2[i][2] = fma2(svp, vB.x, acc2[i][2]);
                    acc2[i][3] = fma2(svp, vB.y, acc2[i][3]);
                }
            }
        }
        #pragma unroll
        for (int i = 0; i < 4; i++) {
            ulonglong2 o0, o1;
            o0.x = acc2[i][0]; o0.y = acc2[i][1];
            o1.x = acc2[i][2]; o1.y = acc2[i][3];
            *(ulonglong2*)&Qs[IDX(ty * 4 + i, tx * 2)]     = o0;
            *(ulonglong2*)&Qs[IDX(ty * 4 + i, tx * 2 + 1)] = o1;
        }
    }
    __syncthreads();

    // softmax over d_k (64) per row -> out
    {
        const int lane = tid & 31;
        const int w = tid >> 5;
        const float* Qf = (const float*)Qs;
        for (int b = w; b < 64; b += 4) {
            const int c0 = lane, c1 = lane + 32;
            const float x0 = Qf[IDX(b, c0 >> 2) * 4 + (c0 & 3)];
            const float x1 = Qf[IDX(b, c1 >> 2) * 4 + (c1 & 3)];
            float mx = fmaxf(x0, x1);
            #pragma unroll
            for (int o2 = 16; o2 > 0; o2 >>= 1)
                mx = fmaxf(mx, __shfl_xor_sync(0xffffffffu, mx, o2));
            const float e0 = __expf(x0 - mx);
            const float e1 = __expf(x1 - mx);
            float sum = e0 + e1;
            #pragma unroll
            for (int o2 = 16; o2 > 0; o2 >>= 1)
                sum += __shfl_xor_sync(0xffffffffu, sum, o2);
            const float inv = 1.0f / sum;
            const size_t og = base + (size_t)b * DMODEL;
            out[og + c0] = e0 * inv;
            out[og + c1] = e1 * inv;
        }
    }
}

// ---------------------------------------------------------------------------
// Launch
// ---------------------------------------------------------------------------
extern "C" void kernel_launch(void* const* d_in, const int* in_sizes, int n_in,
                              void* d_out, int out_size)
{
    const float* K_in = (const float*)d_in[0];
    const float* V_in = (const float*)d_in[1];
    const int*   msk  = (const int*)d_in[2];
    const float* GT   = (const float*)d_in[3];
    const float* Wq   = (const float*)d_in[4];
    const float* bq   = (const float*)d_in[5];
    const float* Wk   = (const float*)d_in[6];
    const float* bk   = (const float*)d_in[7];
    const float* Wv   = (const float*)d_in[8];
    const float* bv   = (const float*)d_in[9];
    const float* Wo   = (const float*)d_in[10];
    const float* bo   = (const float*)d_in[11];
    float* out = (float*)d_out;

    float *gq, *gk, *gv, *gc;
    __half *whi, *wlo;
    cudaGetSymbolAddress((void**)&gq, g_q);
    cudaGetSymbolAddress((void**)&gk, g_k);
    cudaGetSymbolAddress((void**)&gv, g_v);
    cudaGetSymbolAddress((void**)&gc, g_c);
    cudaGetSymbolAddress((void**)&whi, g_whi);
    cudaGetSymbolAddress((void**)&wlo, g_wlo);

    cudaFuncSetAttribute(attn4_kernel,
                         cudaFuncAttributeMaxDynamicSharedMemorySize, AT_SMEM);
    cudaFuncSetAttribute(gemm_v5,
                         cudaFuncAttributeMaxDynamicSharedMemorySize, GEMM_SMEM);

    dim3 sg(1024, 4), sbk(256);
    split_all<<<sg, sbk>>>(Wq, Wk, Wv, Wo, whi, wlo);

    dim3 gg(DMODEL / 256, M_TOT / 128);   // (4, 512)
    dim3 gb(GT_THR);

    gemm_v5<<<gg, gb, GEMM_SMEM>>>(GT,   whi,               wlo,               bq, gq);
    gemm_v5<<<gg, gb, GEMM_SMEM>>>(K_in, whi + 1048576,     wlo + 1048576,     bk, gk);
    gemm_v5<<<gg, gb, GEMM_SMEM>>>(V_in, whi + 2 * 1048576, wlo + 2 * 1048576, bv, gv);
    attn4_kernel<<<dim3(SLEN, NH), 128, AT_SMEM>>>(gq, gk, gv, msk, gc);
    gemm_v5<<<gg, gb, GEMM_SMEM>>>(gc, whi + 3 * 1048576, wlo + 3 * 1048576, bo, out);
}

// round 15
// speedup vs baseline: 1.1590x; 1.0845x over previous
#include <cuda_runtime.h>
#include <cuda_fp16.h>
#include <cstdint>

// Problem constants
#define SLEN 1024
#define BSZ  64
#define DMODEL 1024
#define NH   16
#define DKH  64
#define M_TOT (SLEN * BSZ)   // 65536

// Scratch
__device__ float g_q[67108864];
__device__ float g_k[67108864];
__device__ float g_v[67108864];
__device__ float g_c[67108864];
__device__ __half g_whi[4 * 1048576];   // 4 weights, hi
__device__ __half g_wlo[4 * 1048576];   // 4 weights, lo

// ---------------------------------------------------------------------------
// PTX helpers
// ---------------------------------------------------------------------------
__device__ __forceinline__ uint32_t smem_u32(const void* p) {
    uint32_t a;
    asm("{ .reg .u64 t; cvta.to.shared.u64 t, %1; cvt.u32.u64 %0, t; }"
        : "=r"(a) : "l"(p));
    return a;
}
__device__ __forceinline__ void cp16(uint32_t dst, const void* src) {
    asm volatile("cp.async.cg.shared.global [%0], [%1], 16;"
                 :: "r"(dst), "l"(src));
}
#define CP_COMMIT() asm volatile("cp.async.commit_group;" ::: "memory")
#define CP_WAIT1()  asm volatile("cp.async.wait_group 1;" ::: "memory")
#define CP_WAIT0()  asm volatile("cp.async.wait_group 0;" ::: "memory")

__device__ __forceinline__ void ldsm_x4(uint32_t& r0, uint32_t& r1,
                                        uint32_t& r2, uint32_t& r3, uint32_t a) {
    asm volatile("ldmatrix.sync.aligned.m8n8.x4.shared.b16 {%0,%1,%2,%3}, [%4];"
                 : "=r"(r0), "=r"(r1), "=r"(r2), "=r"(r3) : "r"(a));
}
__device__ __forceinline__ void mma16816(float* d, const uint32_t* a,
                                         const uint32_t* b) {
    asm volatile(
        "mma.sync.aligned.m16n8k16.row.col.f32.f16.f16.f32 "
        "{%0,%1,%2,%3}, {%4,%5,%6,%7}, {%8,%9}, {%0,%1,%2,%3};"
        : "+f"(d[0]), "+f"(d[1]), "+f"(d[2]), "+f"(d[3])
        : "r"(a[0]), "r"(a[1]), "r"(a[2]), "r"(a[3]), "r"(b[0]), "r"(b[1]));
}

// ---------------------------------------------------------------------------
// All-weights split fp32 -> (hi, lo) fp16, one launch. blockIdx.y = weight.
// ---------------------------------------------------------------------------
__global__ void __launch_bounds__(256) split_all(
    const float* __restrict__ w0, const float* __restrict__ w1,
    const float* __restrict__ w2, const float* __restrict__ w3,
    __half* __restrict__ hi, __half* __restrict__ lo)
{
    const int wsel = blockIdx.y;
    const float* in = (wsel == 0) ? w0 : (wsel == 1) ? w1 :
                      (wsel == 2) ? w2 : w3;
    const int i = blockIdx.x * blockDim.x + threadIdx.x;   // 0..262143
    const float4 v = ((const float4*)in)[i];
    __half h0 = __float2half_rn(v.x);
    __half h1 = __float2half_rn(v.y);
    __half h2 = __float2half_rn(v.z);
    __half h3 = __float2half_rn(v.w);
    __half l0 = __float2half_rn(v.x - __half2float(h0));
    __half l1 = __float2half_rn(v.y - __half2float(h1));
    __half l2 = __float2half_rn(v.z - __half2float(h2));
    __half l3 = __float2half_rn(v.w - __half2float(h3));
    const size_t o = (size_t)wsel * 1048576 + (size_t)i * 4;
    __half2* hp = (__half2*)(hi + o);
    __half2* lp = (__half2*)(lo + o);
    hp[0] = __halves2half2(h0, h1);
    hp[1] = __halves2half2(h2, h3);
    lp[0] = __halves2half2(l0, l1);
    lp[1] = __halves2half2(l2, l3);
}

// ---------------------------------------------------------------------------
// fp16-split GEMM v5 (R8 config, best measured): CTA 128x256, 16 warps
// (2m x 8n), warp tile 64x32, KC=64 (16 chunks), 2 stages x 108KB, 1 CTA/SM.
// acc += Ahi*Whi + Ahi*Wlo + Alo*Whi  (fp32 accumulate).
// ---------------------------------------------------------------------------
#define KC 64
#define LDH 72
#define ROWB (LDH * 2)                    // 144
#define A_TILE_B (128 * ROWB)             // 18432
#define B_TILE_B (256 * ROWB)             // 36864
#define OFF_ALO  (A_TILE_B)
#define OFF_BHI  (2 * A_TILE_B)
#define OFF_BLO  (2 * A_TILE_B + B_TILE_B)
#define STG_B    (2 * A_TILE_B + 2 * B_TILE_B)   // 110592
#define GEMM_SMEM (2 * STG_B)                    // 221184
#define NCHUNK 16
#define GT_THR 512

__device__ __forceinline__ void ldgA(const float* __restrict__ A,
                                     int bm, int k0, int tid, float4* pf)
{
    #pragma unroll
    for (int p = 0; p < 4; p++) {
        const int idx = p * GT_THR + tid;
        const int row = idx >> 4;
        const int q   = idx & 15;
        pf[p] = *(const float4*)(A + (size_t)(bm + row) * DMODEL + k0 + q * 4);
    }
}

__device__ __forceinline__ void stsA(char* smem_base, int stg_off,
                                     int tid, const float4* pf)
{
    #pragma unroll
    for (int p = 0; p < 4; p++) {
        const int idx = p * GT_THR + tid;
        const int row = idx >> 4;
        const int q   = idx & 15;
        const float4 v = pf[p];
        __half2 h01 = __floats2half2_rn(v.x, v.y);
        __half2 h23 = __floats2half2_rn(v.z, v.w);
        __half2 l01 = __floats2half2_rn(v.x - __low2float(h01),
                                        v.y - __high2float(h01));
        __half2 l23 = __floats2half2_rn(v.z - __low2float(h23),
                                        v.w - __high2float(h23));
        char* d = smem_base + stg_off + row * ROWB + q * 8;
        *(__half2*)(d)               = h01;
        *(__half2*)(d + 4)           = h23;
        *(__half2*)(d + OFF_ALO)     = l01;
        *(__half2*)(d + OFF_ALO + 4) = l23;
    }
}

__device__ __forceinline__ void cpB(uint32_t stg, const __half* __restrict__ Whi,
                                    const __half* __restrict__ Wlo,
                                    int bn, int k0, int tid)
{
    #pragma unroll
    for (int p = 0; p < 4; p++) {
        const int idx = p * GT_THR + tid;
        const int row = idx >> 3;
        const int qq  = idx & 7;
        const uint32_t d = stg + OFF_BHI + row * ROWB + qq * 16;
        const size_t g = (size_t)(bn + row) * DMODEL + k0 + qq * 8;
        cp16(d, Whi + g);
        cp16(d + (OFF_BLO - OFF_BHI), Wlo + g);
    }
}

__global__ void __launch_bounds__(GT_THR, 1) gemm_v5(
    const float* __restrict__ A, const __half* __restrict__ Whi,
    const __half* __restrict__ Wlo, const float* __restrict__ bias,
    float* __restrict__ C)
{
    extern __shared__ char smem[];
    const uint32_t sb = smem_u32(smem);
    const int tid = threadIdx.x;
    const int lane = tid & 31;
    const int wid = tid >> 5;
    const int bm = blockIdx.y * 128;
    const int bn = blockIdx.x * 256;
    const int wm = (wid & 1) * 64;
    const int wn = (wid >> 1) * 32;

    float acc[4][4][4];
    #pragma unroll
    for (int i = 0; i < 4; i++)
        #pragma unroll
        for (int j = 0; j < 4; j++)
            #pragma unroll
            for (int x = 0; x < 4; x++) acc[i][j][x] = 0.0f;

    float4 pf[4];

    ldgA(A, bm, 0, tid, pf);
    stsA(smem, 0, tid, pf);
    cpB(sb, Whi, Wlo, bn, 0, tid);
    CP_COMMIT();
    ldgA(A, bm, KC, tid, pf);
    cpB(sb + STG_B, Whi, Wlo, bn, KC, tid);
    CP_COMMIT();
    CP_WAIT1();
    __syncthreads();

    const int at = lane >> 3, ar = lane & 7;
    const int a_row_off = ((at & 1) << 3) + ar;
    const int a_kcol8   = ((at >> 1) << 3);
    const int b_row_off = ((lane >> 4) << 3) + (lane & 7);
    const int b_kcol8   = (((lane >> 3) & 1) << 3);

    #pragma unroll 1
    for (int c = 0; c < NCHUNK; c++) {
        const int s = c & 1;
        const uint32_t stg = sb + s * STG_B;

        if (c + 1 < NCHUNK)
            stsA(smem, (s ^ 1) * STG_B, tid, pf);
        if (c + 2 < NCHUNK)
            ldgA(A, bm, (c + 2) * KC, tid, pf);

        #pragma unroll
        for (int ks = 0; ks < 4; ks++) {
            uint32_t af[4][4], bh[2][4], bl[2][4];
            const int akb = (ks * 16 + a_kcol8) * 2;
            const int bkb = (ks * 16 + b_kcol8) * 2;
            #pragma unroll
            for (int i = 0; i < 4; i++) {
                const uint32_t ra =
                    stg + (wm + i * 16 + a_row_off) * ROWB + akb;
                ldsm_x4(af[i][0], af[i][1], af[i][2], af[i][3], ra);
            }
            #pragma unroll
            for (int jj = 0; jj < 2; jj++) {
                const uint32_t rb =
                    stg + (wn + jj * 16 + b_row_off) * ROWB + bkb;
                ldsm_x4(bh[jj][0], bh[jj][1], bh[jj][2], bh[jj][3],
                        rb + OFF_BHI);
                ldsm_x4(bl[jj][0], bl[jj][1], bl[jj][2], bl[jj][3],
                        rb + OFF_BLO);
            }
            #pragma unroll
            for (int i = 0; i < 4; i++)
                #pragma unroll
                for (int j = 0; j < 4; j++)
                    mma16816(acc[i][j], af[i], &bh[j >> 1][(j & 1) * 2]);
            #pragma unroll
            for (int i = 0; i < 4; i++)
                #pragma unroll
                for (int j = 0; j < 4; j++)
                    mma16816(acc[i][j], af[i], &bl[j >> 1][(j & 1) * 2]);
            #pragma unroll
            for (int i = 0; i < 4; i++) {
                const uint32_t ra =
                    stg + (wm + i * 16 + a_row_off) * ROWB + akb;
                ldsm_x4(af[i][0], af[i][1], af[i][2], af[i][3],
                        ra + OFF_ALO);
            }
            #pragma unroll
            for (int i = 0; i < 4; i++)
                #pragma unroll
                for (int j = 0; j < 4; j++)
                    mma16816(acc[i][j], af[i], &bh[j >> 1][(j & 1) * 2]);
        }

        CP_WAIT0();
        __syncthreads();
        if (c + 2 < NCHUNK) {
            cpB(stg, Whi, Wlo, bn, (c + 2) * KC, tid);
            CP_COMMIT();
        }
    }

    #pragma unroll
    for (int i = 0; i < 4; i++) {
        const int r0 = bm + wm + i * 16 + (lane >> 2);
        #pragma unroll
        for (int j = 0; j < 4; j++) {
            const int c0 = bn + wn + j * 8 + ((lane & 3) << 1);
            const float b0 = bias[c0], b1 = bias[c0 + 1];
            float2 v0 = make_float2(acc[i][j][0] + b0, acc[i][j][1] + b1);
            float2 v1 = make_float2(acc[i][j][2] + b0, acc[i][j][3] + b1);
            *(float2*)(C + (size_t)r0 * DMODEL + c0) = v0;
            *(float2*)(C + (size_t)(r0 + 8) * DMODEL + c0) = v1;
        }
    }
}

// ---------------------------------------------------------------------------
// Attention core v5: HMMA fp16-split, one block per (s, h), 128 threads
// (4 warps, each owns m16 rows of the 64x64 output).
// smem tiles: padded rows of 72 halves (144B), same ldsm-safe layout as GEMM.
//   Q hi/lo, K hi/lo   : row = bs index, col = dk     (phase 1: S = Q K^T)
//   Vt hi/lo           : row = dk, col = bs (V transposed at load)
//   S hi/lo            : written between phases       (phase 2: A = S Vt^T)
// All three split-products accumulated per phase (hi*hi + hi*lo + lo*hi).
// ---------------------------------------------------------------------------
#define AROWB 144
#define ATILE (64 * AROWB)        // 9216
#define T_QHI 0
#define T_QLO (1 * ATILE)
#define T_KHI (2 * ATILE)
#define T_KLO (3 * ATILE)
#define T_VHI (4 * ATILE)
#define T_VLO (5 * ATILE)
#define T_SHI (6 * ATILE)
#define T_SLO (7 * ATILE)
#define AT5_SMEM (8 * ATILE)      // 73728

__global__ void __launch_bounds__(128) attn5_kernel(
    const float* __restrict__ q, const float* __restrict__ k,
    const float* __restrict__ v, const int* __restrict__ mask,
    float* __restrict__ out)
{
    extern __shared__ char smem[];
    const uint32_t sb = smem_u32(smem);
    __shared__ float s_mv;

    const int s = blockIdx.x;
    const int h = blockIdx.y;
    const int tid = threadIdx.x;
    const int lane = tid & 31;
    const int wid = tid >> 5;          // 0..3, warp owns rows wid*16..+15
    const size_t base = ((size_t)s * BSZ) * DMODEL + (size_t)h * DKH;

    // ---- load + split Q, K (row-major) and V (transposed) ----
    #pragma unroll
    for (int p = 0; p < 8; p++) {
        const int i = p * 128 + tid;       // 0..1023
        const int b = i >> 4;
        const int d4 = (i & 15) << 2;
        const size_t gm = base + (size_t)b * DMODEL + d4;
        const float4 qv = *(const float4*)(q + gm);
        const float4 kv = *(const float4*)(k + gm);
        const float4 vv = *(const float4*)(v + gm);

        __half2 qh01 = __floats2half2_rn(qv.x, qv.y);
        __half2 qh23 = __floats2half2_rn(qv.z, qv.w);
        __half2 ql01 = __floats2half2_rn(qv.x - __low2float(qh01),
                                         qv.y - __high2float(qh01));
        __half2 ql23 = __floats2half2_rn(qv.z - __low2float(qh23),
                                         qv.w - __high2float(qh23));
        char* dq = smem + T_QHI + b * AROWB + d4 * 2;
        *(__half2*)(dq)     = qh01;
        *(__half2*)(dq + 4) = qh23;
        *(__half2*)(dq + (T_QLO - T_QHI))     = ql01;
        *(__half2*)(dq + (T_QLO - T_QHI) + 4) = ql23;

        __half2 kh01 = __floats2half2_rn(kv.x, kv.y);
        __half2 kh23 = __floats2half2_rn(kv.z, kv.w);
        __half2 kl01 = __floats2half2_rn(kv.x - __low2float(kh01),
                                         kv.y - __high2float(kh01));
        __half2 kl23 = __floats2half2_rn(kv.z - __low2float(kh23),
                                         kv.w - __high2float(kh23));
        char* dk_ = smem + T_KHI + b * AROWB + d4 * 2;
        *(__half2*)(dk_)     = kh01;
        *(__half2*)(dk_ + 4) = kh23;
        *(__half2*)(dk_ + (T_KLO - T_KHI))     = kl01;
        *(__half2*)(dk_ + (T_KLO - T_KHI) + 4) = kl23;

        // V transposed: Vt[d][b] = V[b][d]
        #pragma unroll
        for (int e = 0; e < 4; e++) {
            const float f = (e == 0) ? vv.x : (e == 1) ? vv.y :
                            (e == 2) ? vv.z : vv.w;
            const __half hh = __float2half_rn(f);
            const __half hl = __float2half_rn(f - __half2float(hh));
            *(__half*)(smem + T_VHI + (d4 + e) * AROWB + b * 2) = hh;
            *(__half*)(smem + T_VLO + (d4 + e) * AROWB + b * 2) = hl;
        }
    }
    if (tid < 32) {
        int a = 0;
        #pragma unroll
        for (int b = tid; b < 64; b += 32) {
            const int m = mask[b * SLEN + s];
            a += m * m;
        }
        #pragma unroll
        for (int o2 = 16; o2 > 0; o2 >>= 1)
            a += __shfl_xor_sync(0xffffffffu, a, o2);
        if (tid == 0) s_mv = (float)a;
    }
    __syncthreads();
    const bool masked = (s_mv == 0.0f);

    // fragment address components (identical formulas to the GEMM)
    const int at = lane >> 3, ar = lane & 7;
    const int a_row_off = ((at & 1) << 3) + ar;
    const int a_kcol8   = ((at >> 1) << 3);
    const int b_row_off = ((lane >> 4) << 3) + (lane & 7);
    const int b_kcol8   = (((lane >> 3) & 1) << 3);
    const int wm = wid * 16;

    if (!masked) {
        // ---- phase 1: S = Q K^T / 8 ----
        {
            float acc[8][4];
            #pragma unroll
            for (int j = 0; j < 8; j++)
                #pragma unroll
                for (int x = 0; x < 4; x++) acc[j][x] = 0.0f;

            #pragma unroll
            for (int ks = 0; ks < 4; ks++) {
                uint32_t ah[4], al[4], bh[4][4], bl[4][4];
                const int akb = (ks * 16 + a_kcol8) * 2;
                const int bkb = (ks * 16 + b_kcol8) * 2;
                const uint32_t ra = sb + T_QHI + (wm + a_row_off) * AROWB + akb;
                ldsm_x4(ah[0], ah[1], ah[2], ah[3], ra);
                ldsm_x4(al[0], al[1], al[2], al[3], ra + (T_QLO - T_QHI));
                #pragma unroll
                for (int jj = 0; jj < 4; jj++) {
                    const uint32_t rb =
                        sb + T_KHI + (jj * 16 + b_row_off) * AROWB + bkb;
                    ldsm_x4(bh[jj][0], bh[jj][1], bh[jj][2], bh[jj][3], rb);
                    ldsm_x4(bl[jj][0], bl[jj][1], bl[jj][2], bl[jj][3],
                            rb + (T_KLO - T_KHI));
                }
                #pragma unroll
                for (int j = 0; j < 8; j++)
                    mma16816(acc[j], ah, &bh[j >> 1][(j & 1) * 2]);
                #pragma unroll
                for (int j = 0; j < 8; j++)
                    mma16816(acc[j], ah, &bl[j >> 1][(j & 1) * 2]);
                #pragma unroll
                for (int j = 0; j < 8; j++)
                    mma16816(acc[j], al, &bh[j >> 1][(j & 1) * 2]);
            }

            // store S hi/lo (scaled)
            const int r0 = wm + (lane >> 2);
            const int cb = (lane & 3) << 1;
            #pragma unroll
            for (int j = 0; j < 8; j++) {
                const int cOff = (j * 8 + cb) * 2;
                const float v00 = acc[j][0] * 0.125f;
                const float v01 = acc[j][1] * 0.125f;
                const float v10 = acc[j][2] * 0.125f;
                const float v11 = acc[j][3] * 0.125f;
                __half2 h0 = __floats2half2_rn(v00, v01);
                __half2 l0 = __floats2half2_rn(v00 - __low2float(h0),
                                               v01 - __high2float(h0));
                __half2 h1 = __floats2half2_rn(v10, v11);
                __half2 l1 = __floats2half2_rn(v10 - __low2float(h1),
                                               v11 - __high2float(h1));
                *(__half2*)(smem + T_SHI + r0 * AROWB + cOff) = h0;
                *(__half2*)(smem + T_SLO + r0 * AROWB + cOff) = l0;
                *(__half2*)(smem + T_SHI + (r0 + 8) * AROWB + cOff) = h1;
                *(__half2*)(smem + T_SLO + (r0 + 8) * AROWB + cOff) = l1;
            }
        }
        __syncthreads();

        // ---- phase 2: attn = S Vt^T, then softmax over dk ----
        {
            float acc[8][4];
            #pragma unroll
            for (int j = 0; j < 8; j++)
                #pragma unroll
                for (int x = 0; x < 4; x++) acc[j][x] = 0.0f;

            #pragma unroll
            for (int ks = 0; ks < 4; ks++) {
                uint32_t ah[4], al[4], bh[4][4], bl[4][4];
                const int akb = (ks * 16 + a_kcol8) * 2;
                const int bkb = (ks * 16 + b_kcol8) * 2;
                const uint32_t ra = sb + T_SHI + (wm + a_row_off) * AROWB + akb;
                ldsm_x4(ah[0], ah[1], ah[2], ah[3], ra);
                ldsm_x4(al[0], al[1], al[2], al[3], ra + (T_SLO - T_SHI));
                #pragma unroll
                for (int jj = 0; jj < 4; jj++) {
                    const uint32_t rb =
                        sb + T_VHI + (jj * 16 + b_row_off) * AROWB + bkb;
                    ldsm_x4(bh[jj][0], bh[jj][1], bh[jj][2], bh[jj][3], rb);
                    ldsm_x4(bl[jj][0], bl[jj][1], bl[jj][2], bl[jj][3],
                            rb + (T_VLO - T_VHI));
                }
                #pragma unroll
                for (int j = 0; j < 8; j++)
                    mma16816(acc[j], ah, &bh[j >> 1][(j & 1) * 2]);
                #pragma unroll
                for (int j = 0; j < 8; j++)
                    mma16816(acc[j], ah, &bl[j >> 1][(j & 1) * 2]);
                #pragma unroll
                for (int j = 0; j < 8; j++)
                    mma16816(acc[j], al, &bh[j >> 1][(j & 1) * 2]);
            }

            // softmax over dk (cols): rows r0 (acc[j][0..1]) and r0+8 (acc[j][2..3]);
            // the 4 lanes of a quad (lane>>2 equal) jointly own each row.
            float mx0 = -1e30f, mx1 = -1e30f;
            #pragma unroll
            for (int j = 0; j < 8; j++) {
                mx0 = fmaxf(mx0, fmaxf(acc[j][0], acc[j][1]));
                mx1 = fmaxf(mx1, fmaxf(acc[j][2], acc[j][3]));
            }
            #pragma unroll
            for (int d = 1; d <= 2; d <<= 1) {
                mx0 = fmaxf(mx0, __shfl_xor_sync(0xffffffffu, mx0, d));
                mx1 = fmaxf(mx1, __shfl_xor_sync(0xffffffffu, mx1, d));
            }
            float sm0 = 0.0f, sm1 = 0.0f;
            #pragma unroll
            for (int j = 0; j < 8; j++) {
                acc[j][0] = __expf(acc[j][0] - mx0);
                acc[j][1] = __expf(acc[j][1] - mx0);
                acc[j][2] = __expf(acc[j][2] - mx1);
                acc[j][3] = __expf(acc[j][3] - mx1);
                sm0 += acc[j][0] + acc[j][1];
                sm1 += acc[j][2] + acc[j][3];
            }
            #pragma unroll
            for (int d = 1; d <= 2; d <<= 1) {
                sm0 += __shfl_xor_sync(0xffffffffu, sm0, d);
                sm1 += __shfl_xor_sync(0xffffffffu, sm1, d);
            }
            const float inv0 = 1.0f / sm0;
            const float inv1 = 1.0f / sm1;

            const int r0 = wm + (lane >> 2);
            const int cb = (lane & 3) << 1;
            #pragma unroll
            for (int j = 0; j < 8; j++) {
                const int c0 = j * 8 + cb;
                *(float2*)(out + base + (size_t)r0 * DMODEL + c0) =
                    make_float2(acc[j][0] * inv0, acc[j][1] * inv0);
                *(float2*)(out + base + (size_t)(r0 + 8) * DMODEL + c0) =
                    make_float2(acc[j][2] * inv1, acc[j][3] * inv1);
            }
        }
    } else {
        // masked (probability ~2^-64): attn row = -1e9 * colsum(V), same for
        // every b; exact fp32 fallback via Vt hi+lo.
        float* ybuf = (float*)(smem + T_SHI);          // y[64]
        float* rbuf = (float*)(smem + T_SHI + 256);    // softmax row[64]
        if (tid < 64) {
            float cs = 0.0f;
            for (int kk = 0; kk < 64; kk++) {
                const float vh = __half2float(
                    *(__half*)(smem + T_VHI + tid * AROWB + kk * 2));
                const float vl = __half2float(
                    *(__half*)(smem + T_VLO + tid * AROWB + kk * 2));
                cs += vh + vl;
            }
            ybuf[tid] = -1e9f * cs;
        }
        __syncthreads();
        if (tid < 32) {
            const float x0 = ybuf[tid], x1 = ybuf[tid + 32];
            float mx = fmaxf(x0, x1);
            #pragma unroll
            for (int o2 = 16; o2 > 0; o2 >>= 1)
                mx = fmaxf(mx, __shfl_xor_sync(0xffffffffu, mx, o2));
            const float e0 = __expf(x0 - mx);
            const float e1 = __expf(x1 - mx);
            float sum = e0 + e1;
            #pragma unroll
            for (int o2 = 16; o2 > 0; o2 >>= 1)
                sum += __shfl_xor_sync(0xffffffffu, sum, o2);
            const float inv = 1.0f / sum;
            rbuf[tid] = e0 * inv;
            rbuf[tid + 32] = e1 * inv;
        }
        __syncthreads();
        for (int idx = tid; idx < 64 * 64; idx += 128) {
            const int b = idx >> 6;
            const int n = idx & 63;
            out[base + (size_t)b * DMODEL + n] = rbuf[n];
        }
    }
}

// ---------------------------------------------------------------------------
// Launch
// ---------------------------------------------------------------------------
extern "C" void kernel_launch(void* const* d_in, const int* in_sizes, int n_in,
                              void* d_out, int out_size)
{
    const float* K_in = (const float*)d_in[0];
    const float* V_in = (const float*)d_in[1];
    const int*   msk  = (const int*)d_in[2];
    const float* GT   = (const float*)d_in[3];
    const float* Wq   = (const float*)d_in[4];
    const float* bq   = (const float*)d_in[5];
    const float* Wk   = (const float*)d_in[6];
    const float* bk   = (const float*)d_in[7];
    const float* Wv   = (const float*)d_in[8];
    const float* bv   = (const float*)d_in[9];
    const float* Wo   = (const float*)d_in[10];
    const float* bo   = (const float*)d_in[11];
    float* out = (float*)d_out;

    float *gq, *gk, *gv, *gc;
    __half *whi, *wlo;
    cudaGetSymbolAddress((void**)&gq, g_q);
    cudaGetSymbolAddress((void**)&gk, g_k);
    cudaGetSymbolAddress((void**)&gv, g_v);
    cudaGetSymbolAddress((void**)&gc, g_c);
    cudaGetSymbolAddress((void**)&whi, g_whi);
    cudaGetSymbolAddress((void**)&wlo, g_wlo);

    cudaFuncSetAttribute(attn5_kernel,
                         cudaFuncAttributeMaxDynamicSharedMemorySize, AT5_SMEM);
    cudaFuncSetAttribute(gemm_v5,
                         cudaFuncAttributeMaxDynamicSharedMemorySize, GEMM_SMEM);

    dim3 sg(1024, 4), sbk(256);
    split_all<<<sg, sbk>>>(Wq, Wk, Wv, Wo, whi, wlo);

    dim3 gg(DMODEL / 256, M_TOT / 128);   // (4, 512)
    dim3 gb(GT_THR);

    gemm_v5<<<gg, gb, GEMM_SMEM>>>(GT,   whi,               wlo,               bq, gq);
    gemm_v5<<<gg, gb, GEMM_SMEM>>>(K_in, whi + 1048576,     wlo + 1048576,     bk, gk);
    gemm_v5<<<gg, gb, GEMM_SMEM>>>(V_in, whi + 2 * 1048576, wlo + 2 * 1048576, bv, gv);
    attn5_kernel<<<dim3(SLEN, NH), 128, AT5_SMEM>>>(gq, gk, gv, msk, gc);
    gemm_v5<<<gg, gb, GEMM_SMEM>>>(gc, whi + 3 * 1048576, wlo + 3 * 1048576, bo, out);
}